// round 1
// baseline (speedup 1.0000x reference)
#include <cuda_runtime.h>
#include <cuda_bf16.h>

// Gram-Schmidt over M=4 model outputs, per (batch, channel) vector of D=1024.
// x: [M=4, B=128, C=64, D=1024] fp32. out: same shape.
// One CTA per (b,c) pair: 8192 CTAs x 256 threads. Each thread owns 4
// consecutive floats (one float4) of each of the 4 vectors -> all state in
// registers; single pass over HBM (134 MB read + 134 MB write).

#define NTHREADS 256
#define M_DIM 4
#define D_DIM 1024
#define NPAIRS 8192            // B*C = 128*64
#define MSTRIDE 8388608LL      // B*C*D = 8192*1024

__device__ __forceinline__ float warp_sum(float v) {
    v += __shfl_xor_sync(0xffffffffu, v, 16);
    v += __shfl_xor_sync(0xffffffffu, v, 8);
    v += __shfl_xor_sync(0xffffffffu, v, 4);
    v += __shfl_xor_sync(0xffffffffu, v, 2);
    v += __shfl_xor_sync(0xffffffffu, v, 1);
    return v;
}

// Block-wide sum of K values simultaneously. red must hold K*8 floats.
template <int K>
__device__ __forceinline__ void block_sum(float* vals, float* red, int tid) {
    const int lane = tid & 31;
    const int warp = tid >> 5;
#pragma unroll
    for (int k = 0; k < K; k++) vals[k] = warp_sum(vals[k]);
    if (lane == 0) {
#pragma unroll
        for (int k = 0; k < K; k++) red[k * 8 + warp] = vals[k];
    }
    __syncthreads();
#pragma unroll
    for (int k = 0; k < K; k++) {
        float s = 0.f;
#pragma unroll
        for (int w = 0; w < 8; w++) s += red[k * 8 + w];
        vals[k] = s;
    }
    __syncthreads();  // protect red for next round
}

__device__ __forceinline__ float dot4(float4 a, float4 b) {
    return a.x * b.x + a.y * b.y + a.z * b.z + a.w * b.w;
}

__global__ __launch_bounds__(NTHREADS, 4)
void gram_schmidt_kernel(const float* __restrict__ x, float* __restrict__ out) {
    const int bc  = blockIdx.x;           // 0..8191  -> (b*C + c)
    const int tid = threadIdx.x;          // 0..255
    __shared__ float red[3 * 8];

    // element offset of this thread's float4 within one vector
    const long long base = (long long)bc * D_DIM + (long long)tid * 4;

    // Load all four model vectors' slices into registers (coalesced float4).
    float4 v[M_DIM];
#pragma unroll
    for (int m = 0; m < M_DIM; m++)
        v[m] = *reinterpret_cast<const float4*>(x + (long long)m * MSTRIDE + base);

    float4 bvec[M_DIM];

    // ---- stage 0: normalize v0 ----
    {
        float s = dot4(v[0], v[0]);
        block_sum<1>(&s, red, tid);
        float inv = (s > 0.f) ? rsqrtf(s) : 0.f;
        bvec[0].x = v[0].x * inv; bvec[0].y = v[0].y * inv;
        bvec[0].z = v[0].z * inv; bvec[0].w = v[0].w * inv;
        *reinterpret_cast<float4*>(out + base) = bvec[0];
    }

    // ---- stage 1 ----
    {
        float c = dot4(v[1], bvec[0]);
        block_sum<1>(&c, red, tid);
        float4 w;
        w.x = v[1].x - c * bvec[0].x; w.y = v[1].y - c * bvec[0].y;
        w.z = v[1].z - c * bvec[0].z; w.w = v[1].w - c * bvec[0].w;
        float n = dot4(w, w);
        block_sum<1>(&n, red, tid);
        float inv = (n > 0.f) ? rsqrtf(n) : 0.f;
        bvec[1].x = w.x * inv; bvec[1].y = w.y * inv;
        bvec[1].z = w.z * inv; bvec[1].w = w.w * inv;
        *reinterpret_cast<float4*>(out + MSTRIDE + base) = bvec[1];
    }

    // ---- stage 2 ----
    {
        float c[2];
        c[0] = dot4(v[2], bvec[0]);
        c[1] = dot4(v[2], bvec[1]);
        block_sum<2>(c, red, tid);
        float4 w = v[2];
        w.x -= c[0] * bvec[0].x + c[1] * bvec[1].x;
        w.y -= c[0] * bvec[0].y + c[1] * bvec[1].y;
        w.z -= c[0] * bvec[0].z + c[1] * bvec[1].z;
        w.w -= c[0] * bvec[0].w + c[1] * bvec[1].w;
        float n = dot4(w, w);
        block_sum<1>(&n, red, tid);
        float inv = (n > 0.f) ? rsqrtf(n) : 0.f;
        bvec[2].x = w.x * inv; bvec[2].y = w.y * inv;
        bvec[2].z = w.z * inv; bvec[2].w = w.w * inv;
        *reinterpret_cast<float4*>(out + 2 * MSTRIDE + base) = bvec[2];
    }

    // ---- stage 3 ----
    {
        float c[3];
        c[0] = dot4(v[3], bvec[0]);
        c[1] = dot4(v[3], bvec[1]);
        c[2] = dot4(v[3], bvec[2]);
        block_sum<3>(c, red, tid);
        float4 w = v[3];
        w.x -= c[0] * bvec[0].x + c[1] * bvec[1].x + c[2] * bvec[2].x;
        w.y -= c[0] * bvec[0].y + c[1] * bvec[1].y + c[2] * bvec[2].y;
        w.z -= c[0] * bvec[0].z + c[1] * bvec[1].z + c[2] * bvec[2].z;
        w.w -= c[0] * bvec[0].w + c[1] * bvec[1].w + c[2] * bvec[2].w;
        float n = dot4(w, w);
        block_sum<1>(&n, red, tid);
        float inv = (n > 0.f) ? rsqrtf(n) : 0.f;
        float4 b3;
        b3.x = w.x * inv; b3.y = w.y * inv;
        b3.z = w.z * inv; b3.w = w.w * inv;
        *reinterpret_cast<float4*>(out + 3 * MSTRIDE + base) = b3;
    }
}

extern "C" void kernel_launch(void* const* d_in, const int* in_sizes, int n_in,
                              void* d_out, int out_size) {
    const float* x = (const float*)d_in[0];
    float* out = (float*)d_out;
    gram_schmidt_kernel<<<NPAIRS, NTHREADS>>>(x, out);
}

// round 2
// speedup vs baseline: 1.2727x; 1.2727x over previous
#include <cuda_runtime.h>
#include <cuda_bf16.h>

// Gram-Schmidt over M=4 model outputs, per (batch, channel) vector of D=1024.
// x: [M=4, B=128, C=64, D=1024] fp32, out same shape.
//
// Key idea: all 10 pairwise dots G_ij = <v_i, v_j> are independent of the GS
// recurrence, so compute them in ONE fused block reduction; the GS coefficients
// (lower-triangular T with basis_i = sum_j T_ij v_j) are then pure scalar
// algebra on G, replicated per-thread. 2 barriers total instead of 14.

#define NTHREADS 256
#define M_DIM 4
#define D_DIM 1024
#define NPAIRS 8192            // B*C
#define MSTRIDE 8388608LL      // B*C*D

__device__ __forceinline__ float dot4(float4 a, float4 b) {
    return a.x * b.x + a.y * b.y + a.z * b.z + a.w * b.w;
}

__global__ __launch_bounds__(NTHREADS, 4)
void gram_schmidt_kernel(const float* __restrict__ x, float* __restrict__ out) {
    const int bc   = blockIdx.x;
    const int tid  = threadIdx.x;
    const int lane = tid & 31;
    const int warp = tid >> 5;

    __shared__ float red[8][12];   // per-warp partials, padded row (48B, 16B-aligned)
    __shared__ float gsm[12];      // final Gram entries

    const long long base = (long long)bc * D_DIM + (long long)tid * 4;

    // Load all four vectors' slices (coalesced LDG.128, front-batched for MLP).
    float4 v0 = *reinterpret_cast<const float4*>(x + base);
    float4 v1 = *reinterpret_cast<const float4*>(x + MSTRIDE + base);
    float4 v2 = *reinterpret_cast<const float4*>(x + 2 * MSTRIDE + base);
    float4 v3 = *reinterpret_cast<const float4*>(x + 3 * MSTRIDE + base);

    // 10 pairwise dot partials: order (00)(01)(02)(03)(11)(12)(13)(22)(23)(33)
    float p[10];
    p[0] = dot4(v0, v0); p[1] = dot4(v0, v1); p[2] = dot4(v0, v2);
    p[3] = dot4(v0, v3); p[4] = dot4(v1, v1); p[5] = dot4(v1, v2);
    p[6] = dot4(v1, v3); p[7] = dot4(v2, v2); p[8] = dot4(v2, v3);
    p[9] = dot4(v3, v3);

    // Warp reduction: 10 values packed as 5 x 64-bit shuffles per level.
#pragma unroll
    for (int lvl = 16; lvl >= 1; lvl >>= 1) {
#pragma unroll
        for (int q = 0; q < 5; q++) {
            unsigned long long u =
                ((unsigned long long)__float_as_uint(p[2 * q + 1]) << 32) |
                (unsigned long long)__float_as_uint(p[2 * q]);
            unsigned long long r = __shfl_xor_sync(0xffffffffu, u, lvl);
            p[2 * q]     += __uint_as_float((unsigned)r);
            p[2 * q + 1] += __uint_as_float((unsigned)(r >> 32));
        }
    }

    if (lane == 0) {
        float4* row = reinterpret_cast<float4*>(red[warp]);
        row[0] = make_float4(p[0], p[1], p[2], p[3]);
        row[1] = make_float4(p[4], p[5], p[6], p[7]);
        red[warp][8] = p[8];
        red[warp][9] = p[9];
    }
    __syncthreads();

    // 10 threads finalize across the 8 warps (stride-12 rows: conflict-free).
    if (tid < 10) {
        float s = 0.f;
#pragma unroll
        for (int w = 0; w < 8; w++) s += red[w][tid];
        gsm[tid] = s;
    }
    __syncthreads();

    // Broadcast-read final Gram (LDS.128 x2 + LDS.64).
    float4 ga = *reinterpret_cast<const float4*>(gsm);
    float4 gb = *reinterpret_cast<const float4*>(gsm + 4);
    float  g23 = gsm[8];
    float  g33 = gsm[9];
    const float g00 = ga.x, g01 = ga.y, g02 = ga.z, g03 = ga.w;
    const float g11 = gb.x, g12 = gb.y, g13 = gb.z, g22 = gb.w;

    // ---- scalar GS recurrence on the Gram matrix (replicated per thread) ----
    const float inv0 = (g00 > 0.f) ? rsqrtf(g00) : 0.f;     // T00

    // stage 1
    const float c0 = g01 * inv0;                            // <v1, b0>
    const float n1 = fmaxf(g11 - c0 * c0, 0.f);
    const float inv1 = (n1 > 0.f) ? rsqrtf(n1) : 0.f;
    const float T10 = -c0 * inv0 * inv1;
    const float T11 = inv1;

    // stage 2
    const float d0 = g02 * inv0;                            // <v2, b0>
    const float d1 = T10 * g02 + T11 * g12;                 // <v2, b1>
    const float n2 = fmaxf(g22 - d0 * d0 - d1 * d1, 0.f);
    const float inv2 = (n2 > 0.f) ? rsqrtf(n2) : 0.f;
    const float T20 = inv2 * (-d0 * inv0 - d1 * T10);
    const float T21 = inv2 * (-d1 * T11);
    const float T22 = inv2;

    // stage 3
    const float e0 = g03 * inv0;                            // <v3, b0>
    const float e1 = T10 * g03 + T11 * g13;                 // <v3, b1>
    const float e2 = T20 * g03 + T21 * g13 + T22 * g23;     // <v3, b2>
    const float n3 = fmaxf(g33 - e0 * e0 - e1 * e1 - e2 * e2, 0.f);
    const float inv3 = (n3 > 0.f) ? rsqrtf(n3) : 0.f;
    const float T30 = inv3 * (-e0 * inv0 - e1 * T10 - e2 * T20);
    const float T31 = inv3 * (-e1 * T11 - e2 * T21);
    const float T32 = inv3 * (-e2 * T22);
    const float T33 = inv3;

    // ---- outputs: basis_i = sum_j T_ij v_j ----
    float4 o;
    o.x = inv0 * v0.x; o.y = inv0 * v0.y; o.z = inv0 * v0.z; o.w = inv0 * v0.w;
    *reinterpret_cast<float4*>(out + base) = o;

    o.x = T10 * v0.x + T11 * v1.x; o.y = T10 * v0.y + T11 * v1.y;
    o.z = T10 * v0.z + T11 * v1.z; o.w = T10 * v0.w + T11 * v1.w;
    *reinterpret_cast<float4*>(out + MSTRIDE + base) = o;

    o.x = T20 * v0.x + T21 * v1.x + T22 * v2.x;
    o.y = T20 * v0.y + T21 * v1.y + T22 * v2.y;
    o.z = T20 * v0.z + T21 * v1.z + T22 * v2.z;
    o.w = T20 * v0.w + T21 * v1.w + T22 * v2.w;
    *reinterpret_cast<float4*>(out + 2 * MSTRIDE + base) = o;

    o.x = T30 * v0.x + T31 * v1.x + T32 * v2.x + T33 * v3.x;
    o.y = T30 * v0.y + T31 * v1.y + T32 * v2.y + T33 * v3.y;
    o.z = T30 * v0.z + T31 * v1.z + T32 * v2.z + T33 * v3.z;
    o.w = T30 * v0.w + T31 * v1.w + T32 * v2.w + T33 * v3.w;
    *reinterpret_cast<float4*>(out + 3 * MSTRIDE + base) = o;
}

extern "C" void kernel_launch(void* const* d_in, const int* in_sizes, int n_in,
                              void* d_out, int out_size) {
    const float* x = (const float*)d_in[0];
    float* out = (float*)d_out;
    gram_schmidt_kernel<<<NPAIRS, NTHREADS>>>(x, out);
}